// round 1
// baseline (speedup 1.0000x reference)
#include <cuda_runtime.h>
#include <cstdint>

typedef unsigned long long ULL;

// ---------- packed f32x2 helpers (sm_100+ PTX) ----------
__device__ __forceinline__ ULL pack2(float x) {
    ULL r; asm("mov.b64 %0, {%1, %1};" : "=l"(r) : "f"(x)); return r;
}
__device__ __forceinline__ ULL fma2(ULL a, ULL b, ULL c) {
    ULL d; asm("fma.rn.f32x2 %0, %1, %2, %3;" : "=l"(d) : "l"(a), "l"(b), "l"(c)); return d;
}
__device__ __forceinline__ ULL add2(ULL a, ULL b) {
    ULL d; asm("add.rn.f32x2 %0, %1, %2;" : "=l"(d) : "l"(a), "l"(b)); return d;
}
__device__ __forceinline__ void unpack2(ULL v, float& lo, float& hi) {
    asm("mov.b64 {%0, %1}, %2;" : "=f"(lo), "=f"(hi) : "l"(v));
}

// ---------- problem constants ----------
static constexpr int B = 32, S = 128, E = 512, F = 2048;

// ---------- scratch (no allocations allowed) ----------
__device__ float g_xt[(size_t)S * E * B];   // x transposed: [s][e][b]   (8 MB)
__device__ float g_H [(size_t)S * F * B];   // hidden:        [s][f][b]  (32 MB)
__device__ float g_Y [(size_t)B * S * E];   // pre-LN y:      [b][s][e]  (8 MB)

// ============================================================
// K0: transpose x[b][s][e] -> xt[s][e][b]
// grid (S, E/32), block (32, 8)
// ============================================================
__global__ void k_transpose(const float* __restrict__ x) {
    __shared__ float t[32][33];
    const int s  = blockIdx.x;
    const int e0 = blockIdx.y * 32;
    const int tx = threadIdx.x, ty = threadIdx.y;
#pragma unroll
    for (int r = 0; r < 4; r++) {
        const int b = ty + r * 8;
        t[b][tx] = x[((size_t)b * S + s) * E + e0 + tx];
    }
    __syncthreads();
#pragma unroll
    for (int r = 0; r < 4; r++) {
        const int e = ty + r * 8;
        g_xt[((size_t)s * E + e0 + e) * B + tx] = t[tx][e];
    }
}

// ============================================================
// K1: H[s][f][b] = x_s[32,512] @ W1_s[512,2048] + b1
// grid (F/256, S), block 256. Thread owns one f column, all 32 b
// as 16 packed f32x2 accumulators.
// ============================================================
__global__ __launch_bounds__(256, 2) void k_gemm1(const float* __restrict__ W1,
                                                  const float* __restrict__ b1) {
    __shared__ float sm[12288];                 // 48 KB: xs chunk (32 KB) / ts (33 KB)
    const int s   = blockIdx.y;
    const int tid = threadIdx.x;
    const int f0  = blockIdx.x * 256;
    const int f   = f0 + tid;

    ULL acc[16];
    {
        ULL bb = pack2(b1[s * F + f]);
#pragma unroll
        for (int j = 0; j < 16; j++) acc[j] = bb;
    }

    const float* wp = W1 + (size_t)s * E * F + f;   // element stride over e: F

    for (int ec = 0; ec < 2; ec++) {                // E in 2 chunks of 256
        __syncthreads();
        const float* xsrc = g_xt + ((size_t)s * E + ec * 256) * B;
        for (int i = tid; i < 256 * B; i += 256) sm[i] = xsrc[i];
        __syncthreads();

        const ulonglong2* xv  = (const ulonglong2*)sm;  // [e][b] as 8 x 16B per e
        const float*      wpe = wp + (size_t)ec * 256 * F;

        for (int e0 = 0; e0 < 256; e0 += 8) {
            float w[8];
#pragma unroll
            for (int u = 0; u < 8; u++) w[u] = wpe[(size_t)(e0 + u) * F];
#pragma unroll
            for (int u = 0; u < 8; u++) {
                const ULL ww = pack2(w[u]);
                const ulonglong2* xr = xv + (e0 + u) * 8;
#pragma unroll
                for (int j = 0; j < 8; j++) {
                    ulonglong2 v = xr[j];               // broadcast LDS.128
                    acc[2 * j]     = fma2(v.x, ww, acc[2 * j]);
                    acc[2 * j + 1] = fma2(v.y, ww, acc[2 * j + 1]);
                }
            }
        }
    }

    // stage transpose through SMEM -> coalesced H[s][f][b] store
    __syncthreads();
#pragma unroll
    for (int j = 0; j < 16; j++) {
        float lo, hi; unpack2(acc[j], lo, hi);
        sm[tid * 33 + 2 * j]     = lo;                  // acc[j] = b (2j, 2j+1)
        sm[tid * 33 + 2 * j + 1] = hi;
    }
    __syncthreads();
    float* hdst = g_H + ((size_t)s * F + f0) * B;
    for (int i = tid; i < 256 * B; i += 256)
        hdst[i] = sm[(i >> 5) * 33 + (i & 31)];
}

// ============================================================
// K2: y = H_s[32,2048] @ W2_s[2048,512] + b2 + x  -> g_Y[b][s][e]
// grid (E/256, S), block 256.
// ============================================================
__global__ __launch_bounds__(256, 2) void k_gemm2(const float* __restrict__ W2,
                                                  const float* __restrict__ b2) {
    __shared__ float sm[12288];
    const int s   = blockIdx.y;
    const int tid = threadIdx.x;
    const int n0  = blockIdx.x * 256;
    const int n   = n0 + tid;

    ULL acc[16];
    {
        ULL bb = pack2(b2[s * E + n]);
#pragma unroll
        for (int j = 0; j < 16; j++) acc[j] = bb;
    }

    const float* wp = W2 + (size_t)s * F * E + n;   // element stride over k: E

    for (int kc = 0; kc < 8; kc++) {                // F in 8 chunks of 256
        __syncthreads();
        const float* hsrc = g_H + ((size_t)s * F + kc * 256) * B;
        for (int i = tid; i < 256 * B; i += 256) sm[i] = hsrc[i];
        __syncthreads();

        const ulonglong2* hv  = (const ulonglong2*)sm;
        const float*      wpe = wp + (size_t)kc * 256 * E;

        for (int e0 = 0; e0 < 256; e0 += 8) {
            float w[8];
#pragma unroll
            for (int u = 0; u < 8; u++) w[u] = wpe[(size_t)(e0 + u) * E];
#pragma unroll
            for (int u = 0; u < 8; u++) {
                const ULL ww = pack2(w[u]);
                const ulonglong2* hr = hv + (e0 + u) * 8;
#pragma unroll
                for (int j = 0; j < 8; j++) {
                    ulonglong2 v = hr[j];
                    acc[2 * j]     = fma2(v.x, ww, acc[2 * j]);
                    acc[2 * j + 1] = fma2(v.y, ww, acc[2 * j + 1]);
                }
            }
        }
    }

    // residual: x[b][s][n] read packed from xt[s][n][b]
    {
        const ulonglong2* rv = (const ulonglong2*)(g_xt + ((size_t)s * E + n) * B);
#pragma unroll
        for (int j = 0; j < 8; j++) {
            ulonglong2 r = rv[j];
            acc[2 * j]     = add2(acc[2 * j], r.x);
            acc[2 * j + 1] = add2(acc[2 * j + 1], r.y);
        }
    }

    // stage to [b][n] tile in SMEM -> coalesced g_Y[b][s][n] store
    __syncthreads();
#pragma unroll
    for (int j = 0; j < 16; j++) {
        float lo, hi; unpack2(acc[j], lo, hi);
        sm[(2 * j) * 256 + tid]     = lo;
        sm[(2 * j + 1) * 256 + tid] = hi;
    }
    __syncthreads();
    for (int i = tid; i < 32 * 256; i += 256) {
        const int b = i >> 8, nn = i & 255;
        g_Y[((size_t)b * S + s) * E + n0 + nn] = sm[i];
    }
}

// ============================================================
// K3: LayerNorm over E per (b,s) row. warp per row.
// grid 512, block 256 (8 warps)
// ============================================================
__global__ void k_ln(const float* __restrict__ gamma, const float* __restrict__ beta,
                     float* __restrict__ out) {
    const int warp = threadIdx.x >> 5, lane = threadIdx.x & 31;
    const int row  = blockIdx.x * 8 + warp;          // row = b*S + s, 0..4095
    const float* yr = g_Y + (size_t)row * E;

    float v[16];
    float sum = 0.f, sq = 0.f;
#pragma unroll
    for (int k = 0; k < 16; k++) {
        const float t = yr[lane + 32 * k];
        v[k] = t; sum += t; sq += t * t;
    }
#pragma unroll
    for (int o = 16; o; o >>= 1) {
        sum += __shfl_xor_sync(0xFFFFFFFFu, sum, o);
        sq  += __shfl_xor_sync(0xFFFFFFFFu, sq,  o);
    }
    const float mu   = sum * (1.f / E);
    const float var  = sq * (1.f / E) - mu * mu;
    const float rstd = rsqrtf(var + 1e-5f);

    float* orow = out + (size_t)row * E;
#pragma unroll
    for (int k = 0; k < 16; k++) {
        const int e = lane + 32 * k;
        orow[e] = (v[k] - mu) * rstd * gamma[e] + beta[e];
    }
}

// ============================================================
extern "C" void kernel_launch(void* const* d_in, const int* in_sizes, int n_in,
                              void* d_out, int out_size) {
    const float* x     = (const float*)d_in[0];
    const float* W1    = (const float*)d_in[1];
    const float* b1    = (const float*)d_in[2];
    const float* W2    = (const float*)d_in[3];
    const float* b2    = (const float*)d_in[4];
    const float* gamma = (const float*)d_in[5];
    const float* beta  = (const float*)d_in[6];
    float* out = (float*)d_out;

    k_transpose<<<dim3(S, E / 32), dim3(32, 8)>>>(x);
    k_gemm1<<<dim3(F / 256, S), 256>>>(W1, b1);
    k_gemm2<<<dim3(E / 256, S), 256>>>(W2, b2);
    k_ln<<<(B * S) / 8, 256>>>(gamma, beta, out);
}

// round 6
// speedup vs baseline: 2.4092x; 2.4092x over previous
#include <cuda_runtime.h>
#include <cuda_bf16.h>
#include <cstdint>

static constexpr int B_ = 32, S_ = 128, E_ = 512, F_ = 2048;
static constexpr int KC = 64;   // K per chunk

// per-buffer SMEM block: A_hi 16K | A_lo 16K | B_hi 4K | B_lo 4K = 40960
static constexpr int OFF_A_HI = 0;
static constexpr int OFF_A_LO = 16384;
static constexpr int OFF_B_HI = 32768;
static constexpr int OFF_B_LO = 36864;
static constexpr int BUF_SZ   = 40960;
static constexpr int SM_DYN   = 2 * BUF_SZ + 1024;

// ---- scratch ----
__device__ uint32_t g_H[(size_t)S_ * B_ * F_];   // packed (hi | lo<<16) [s][b][f]
__device__ float    g_Y[(size_t)B_ * S_ * E_];   // pre-LN y [b][s][e]

// ============ helpers ============
__device__ __forceinline__ uint32_t s2u(const void* p) {
    uint32_t a;
    asm("{ .reg .u64 t; cvta.to.shared.u64 t, %1; cvt.u32.u64 %0, t; }" : "=r"(a) : "l"(p));
    return a;
}
__device__ __forceinline__ uint32_t packbf(float lo, float hi) {   // lo -> low 16 bits
    uint32_t r; asm("cvt.rn.bf16x2.f32 %0, %1, %2;" : "=r"(r) : "f"(hi), "f"(lo)); return r;
}
__device__ __forceinline__ float bflo(uint32_t p) { return __uint_as_float(p << 16); }
__device__ __forceinline__ float bfhi(uint32_t p) { return __uint_as_float(p & 0xFFFF0000u); }
__device__ __forceinline__ void sts32(uint32_t a, uint32_t v) {
    asm volatile("st.shared.b32 [%0], %1;" :: "r"(a), "r"(v) : "memory");
}
__device__ __forceinline__ void sts64(uint32_t a, uint32_t v0, uint32_t v1) {
    asm volatile("st.shared.v2.b32 [%0], {%1, %2};" :: "r"(a), "r"(v0), "r"(v1) : "memory");
}
__device__ __forceinline__ void ldmA(uint32_t* r, uint32_t addr) {  // x4 trans: [k][m] -> row-major A frag
    asm volatile("ldmatrix.sync.aligned.m8n8.x4.trans.shared.b16 {%0,%1,%2,%3}, [%4];"
                 : "=r"(r[0]), "=r"(r[1]), "=r"(r[2]), "=r"(r[3]) : "r"(addr));
}
__device__ __forceinline__ void ldmB(uint32_t* r, uint32_t addr) {  // x4: [n][k] -> col-major B frags
    asm volatile("ldmatrix.sync.aligned.m8n8.x4.shared.b16 {%0,%1,%2,%3}, [%4];"
                 : "=r"(r[0]), "=r"(r[1]), "=r"(r[2]), "=r"(r[3]) : "r"(addr));
}
__device__ __forceinline__ void mma16816(float* c, const uint32_t* a, const uint32_t* b) {
    asm volatile(
        "mma.sync.aligned.m16n8k16.row.col.f32.bf16.bf16.f32 "
        "{%0,%1,%2,%3}, {%4,%5,%6,%7}, {%8,%9}, {%0,%1,%2,%3};"
        : "+f"(c[0]), "+f"(c[1]), "+f"(c[2]), "+f"(c[3])
        : "r"(a[0]), "r"(a[1]), "r"(a[2]), "r"(a[3]), "r"(b[0]), "r"(b[1]));
}
__device__ __forceinline__ uint32_t swz(uint32_t off) { return off ^ ((off >> 3) & 0x70); }

// ---- A staging: 64 k-rows x 128 m fp32 -> hi/lo bf16 tiles [k][m], m-contiguous ----
// tile addr(k, mbyte) = k*256 + (mbyte ^ ((k&7)<<4))
__device__ __forceinline__ void stageA(const float* __restrict__ Wbase, int ldw,
                                       uint32_t a_hi, uint32_t a_lo, int t) {
#pragma unroll
    for (int j = 0; j < 8; j++) {
        const int id = j * 1024 + t * 4;
        const int kl = id >> 7;           // 0..63
        const int m  = id & 127;          // multiple of 4
        const float4 v = *(const float4*)(Wbase + (size_t)kl * ldw + m);
        const uint32_t h0 = packbf(v.x, v.y), h1 = packbf(v.z, v.w);
        const uint32_t l0 = packbf(v.x - bflo(h0), v.y - bfhi(h0));
        const uint32_t l1 = packbf(v.z - bflo(h1), v.w - bfhi(h1));
        const uint32_t off = (uint32_t)(kl * 256) + (((uint32_t)(m * 2)) ^ ((uint32_t)(kl & 7) << 4));
        sts64(a_hi + off, h0, h1);
        sts64(a_lo + off, l0, l1);
    }
}

// ---- compute one KC=64 chunk: 12 HMMA per k16-step per warp ----
__device__ __forceinline__ void computeChunk(uint32_t buf, float acc[4][4], int L, int w) {
    const uint32_t offA0 = (uint32_t)((((L >> 4) & 1) * 8 + (L & 7)) * 256)
                         + (((uint32_t)(w * 32 + ((L >> 3) & 1) * 16)) ^ ((uint32_t)(L & 7) << 4));
    const uint32_t aHi = buf + OFF_A_HI, aLo = buf + OFF_A_LO;
    const uint32_t bHi = buf + OFF_B_HI, bLo = buf + OFF_B_LO;
#pragma unroll
    for (int ks = 0; ks < 4; ks++) {
        uint32_t ah[4], al[4], bh[8], bl[8];
        ldmA(ah, aHi + offA0 + ks * 4096);
        ldmA(al, aLo + offA0 + ks * 4096);
#pragma unroll
        for (int P = 0; P < 2; P++) {
            const uint32_t n   = (uint32_t)(P * 16 + ((L >> 4) & 1) * 8 + (L & 7));
            const uint32_t off = n * 128 +
                (((uint32_t)(ks * 32 + ((L >> 3) & 1) * 16)) ^ ((uint32_t)(L & 7) << 4));
            ldmB(bh + P * 4, bHi + off);
            ldmB(bl + P * 4, bLo + off);
        }
#pragma unroll
        for (int q = 0; q < 4; q++) {                 // n-tile q: regs P=q>>1, pair q&1
            const uint32_t* Bh = bh + (q >> 1) * 4 + (q & 1) * 2;
            const uint32_t* Bl = bl + (q >> 1) * 4 + (q & 1) * 2;
            mma16816(acc[q], ah, Bh);
            mma16816(acc[q], ah, Bl);
            mma16816(acc[q], al, Bh);
        }
    }
}

// ============================================================
// GEMM1: D[f(128), b(32)] = sum_e W1[s][e][f0+m] * x[b][s][e] ; +b1 -> g_H packed
// grid (F/128, S), 256 threads
// ============================================================
__global__ __launch_bounds__(256, 2) void k_gemm1(const float* __restrict__ x,
                                                  const float* __restrict__ W1,
                                                  const float* __restrict__ b1) {
    extern __shared__ char smraw[];
    const uint32_t sb = (s2u(smraw) + 1023u) & ~1023u;
    const int s = blockIdx.y, f0 = blockIdx.x * 128;
    const int t = threadIdx.x, w = t >> 5, L = t & 31;

    float acc[4][4];
#pragma unroll
    for (int q = 0; q < 4; q++)
#pragma unroll
        for (int r = 0; r < 4; r++) acc[q][r] = 0.f;

    auto stage = [&](int c) {
        const uint32_t buf = sb + (c & 1) * BUF_SZ;
        stageA(W1 + ((size_t)s * E_ + c * KC) * F_ + f0, F_,
               buf + OFF_A_HI, buf + OFF_A_LO, t);
        // B: x[b][s][e], [n=b][k=e] SW128
#pragma unroll
        for (int i = 0; i < 4; i++) {
            const int id = i * 256 + t, b = id >> 5, ep = id & 31;
            const float2 v = *(const float2*)(x + ((size_t)b * S_ + s) * E_ + c * KC + 2 * ep);
            const uint32_t hp = packbf(v.x, v.y);
            const uint32_t lp = packbf(v.x - bflo(hp), v.y - bfhi(hp));
            const uint32_t off = swz((uint32_t)(b * 128 + ep * 4));
            sts32(buf + OFF_B_HI + off, hp);
            sts32(buf + OFF_B_LO + off, lp);
        }
    };

    stage(0);
    __syncthreads();
    const int NC = E_ / KC;                    // 8
    for (int c = 0; c < NC; c++) {
        if (c + 1 < NC) stage(c + 1);
        computeChunk(sb + (c & 1) * BUF_SZ, acc, L, w);
        __syncthreads();
    }

    // epilogue: pack hi/lo into g_H[s][b][f]
    const int fr = f0 + w * 16 + (L >> 2);
    const float bias0 = b1[s * F_ + fr];
    const float bias1 = b1[s * F_ + fr + 8];
#pragma unroll
    for (int q = 0; q < 4; q++) {
#pragma unroll
        for (int h = 0; h < 2; h++) {
#pragma unroll
            for (int p = 0; p < 2; p++) {
                const float v = acc[q][h * 2 + p] + (h ? bias1 : bias0);
                const float hv = __bfloat162float(__float2bfloat16_rn(v));
                const int b = q * 8 + (L & 3) * 2 + p;
                const int f = fr + h * 8;
                g_H[((size_t)s * B_ + b) * F_ + f] = packbf(v, v - hv);
            }
        }
    }
}

// ============================================================
// GEMM2: D[e(128), b(32)] = sum_f W2[s][f][e0+m] * H[b][f] ; +b2 +x -> g_Y[b][s][e]
// grid (E/128, S), 256 threads
// ============================================================
__global__ __launch_bounds__(256, 2) void k_gemm2(const float* __restrict__ W2,
                                                  const float* __restrict__ b2,
                                                  const float* __restrict__ x) {
    extern __shared__ char smraw[];
    const uint32_t sb = (s2u(smraw) + 1023u) & ~1023u;
    const int s = blockIdx.y, e0 = blockIdx.x * 128;
    const int t = threadIdx.x, w = t >> 5, L = t & 31;

    float acc[4][4];
#pragma unroll
    for (int q = 0; q < 4; q++)
#pragma unroll
        for (int r = 0; r < 4; r++) acc[q][r] = 0.f;

    auto stage = [&](int c) {
        const uint32_t buf = sb + (c & 1) * BUF_SZ;
        stageA(W2 + ((size_t)s * F_ + c * KC) * E_ + e0, E_,
               buf + OFF_A_HI, buf + OFF_A_LO, t);
        // B: packed H[s][b][f] -> split hi/lo, [n=b][k=f] SW128
#pragma unroll
        for (int i = 0; i < 4; i++) {
            const int id = i * 256 + t, b = id >> 5, fp = id & 31;
            const uint2 u = *(const uint2*)(g_H + ((size_t)s * B_ + b) * F_ + c * KC + 2 * fp);
            const uint32_t hp = (u.x & 0xFFFFu) | (u.y << 16);
            const uint32_t lp = (u.x >> 16) | (u.y & 0xFFFF0000u);
            const uint32_t off = swz((uint32_t)(b * 128 + fp * 4));
            sts32(buf + OFF_B_HI + off, hp);
            sts32(buf + OFF_B_LO + off, lp);
        }
    };

    stage(0);
    __syncthreads();
    const int NC = F_ / KC;                    // 32
    for (int c = 0; c < NC; c++) {
        if (c + 1 < NC) stage(c + 1);
        computeChunk(sb + (c & 1) * BUF_SZ, acc, L, w);
        __syncthreads();
    }

    // epilogue: + bias + residual -> g_Y[b][s][e]
    const int er = e0 + w * 16 + (L >> 2);
    const float bias0 = b2[s * E_ + er];
    const float bias1 = b2[s * E_ + er + 8];
#pragma unroll
    for (int q = 0; q < 4; q++) {
#pragma unroll
        for (int h = 0; h < 2; h++) {
#pragma unroll
            for (int p = 0; p < 2; p++) {
                const int b = q * 8 + (L & 3) * 2 + p;
                const int e = er + h * 8;
                const size_t idx = ((size_t)b * S_ + s) * E_ + e;
                g_Y[idx] = acc[q][h * 2 + p] + (h ? bias1 : bias0) + x[idx];
            }
        }
    }
}

// ============================================================
// LayerNorm over E per (b,s) row; warp per row
// ============================================================
__global__ void k_ln(const float* __restrict__ gamma, const float* __restrict__ beta,
                     float* __restrict__ out) {
    const int warp = threadIdx.x >> 5, lane = threadIdx.x & 31;
    const int row  = blockIdx.x * 8 + warp;
    const float* yr = g_Y + (size_t)row * E_;

    float v[16];
    float sum = 0.f, sq = 0.f;
#pragma unroll
    for (int k = 0; k < 16; k++) {
        const float tv = yr[lane + 32 * k];
        v[k] = tv; sum += tv; sq += tv * tv;
    }
#pragma unroll
    for (int o = 16; o; o >>= 1) {
        sum += __shfl_xor_sync(0xFFFFFFFFu, sum, o);
        sq  += __shfl_xor_sync(0xFFFFFFFFu, sq,  o);
    }
    const float mu   = sum * (1.f / E_);
    const float var  = sq * (1.f / E_) - mu * mu;
    const float rstd = rsqrtf(var + 1e-5f);

    float* orow = out + (size_t)row * E_;
#pragma unroll
    for (int k = 0; k < 16; k++) {
        const int e = lane + 32 * k;
        orow[e] = (v[k] - mu) * rstd * gamma[e] + beta[e];
    }
}

// ============================================================
extern "C" void kernel_launch(void* const* d_in, const int* in_sizes, int n_in,
                              void* d_out, int out_size) {
    const float* x     = (const float*)d_in[0];
    const float* W1    = (const float*)d_in[1];
    const float* b1    = (const float*)d_in[2];
    const float* W2    = (const float*)d_in[3];
    const float* b2    = (const float*)d_in[4];
    const float* gamma = (const float*)d_in[5];
    const float* beta  = (const float*)d_in[6];
    float* out = (float*)d_out;

    cudaFuncSetAttribute(k_gemm1, cudaFuncAttributeMaxDynamicSharedMemorySize, SM_DYN);
    cudaFuncSetAttribute(k_gemm2, cudaFuncAttributeMaxDynamicSharedMemorySize, SM_DYN);

    k_gemm1<<<dim3(F_ / 128, S_), 256, SM_DYN>>>(x, W1, b1);
    k_gemm2<<<dim3(E_ / 128, S_), 256, SM_DYN>>>(W2, b2, x);
    k_ln<<<(B_ * S_) / 8, 256>>>(gamma, beta, out);
}